// round 12
// baseline (speedup 1.0000x reference)
#include <cuda_runtime.h>
#include <cuda_bf16.h>
#include <cstdint>

#define BB 8
#define CC 256
#define HH 96
#define WW 96
#define NN (HH*WW)        /* 9216 */
#define KK 16
#define BNT (BB*NN)       /* 73728 */
#define KHH 528           /* 16 + 256 + 256 */

typedef __nv_bfloat16 bf16;

/* ---------------- scratch (device globals) ---------------- */
__device__ float gF   [BB*KK*NN];     /* fp32 F for k_L */
__device__ float gL   [BB*KK*CC];
__device__ float gS   [BB*KK*CC];
__device__ float gAvg [BB*NN];
__device__ float gMax [BB*NN];
__device__ float gBm  [BB*NN];
__device__ float gF4  [BB*4*NN];
__device__ float gCm  [BB*NN];
__device__ float gSsp [BB*HH*HH];
__device__ float gWb  [CC*CC];        /* Wb' = w_h1 . w_beta (fp32, feeds prepWef) */

/* bf16 hi/lo operand arrays, layout [b][k][n] (n contiguous) */
__device__ bf16 gFh [BB*KK*NN],  gFl [BB*KK*NN];
__device__ bf16 gEh [BB*CC*NN],  gEl [BB*CC*NN];   /* Esp */
__device__ bf16 gXh [BB*CC*NN],  gXl [BB*CC*NN];   /* x   */
__device__ bf16 gHhh[BB*CC*NN],  gHhl[BB*CC*NN];   /* Hh  */
__device__ bf16 gMh [BB*CC*NN],  gMl [BB*CC*NN];   /* M   */

/* bf16 hi/lo weights, layout [o][K] (K contiguous) */
__device__ bf16 gWHhH[BB*CC*KHH], gWHhL[BB*CC*KHH];  /* per-batch [b][o][528] */
__device__ bf16 gWMH [CC*2*CC],   gWML [CC*2*CC];
__device__ bf16 gWHMH[CC*2*CC],   gWHML[CC*2*CC];

__device__ __forceinline__ float lrelu_f(float v){ return v >= 0.f ? v : 0.001f*v; }

__device__ __forceinline__ void split_bf(float v, bf16& h, bf16& l){
    h = __float2bfloat16_rn(v);
    l = __float2bfloat16_rn(v - __bfloat162float(h));
}

__device__ __forceinline__ void cpasync16(unsigned int saddr, const void* g){
    asm volatile("cp.async.ca.shared.global [%0], [%1], 16;\n" :: "r"(saddr), "l"(g));
}
__device__ __forceinline__ void cpcommit(){ asm volatile("cp.async.commit_group;\n"); }
__device__ __forceinline__ void cpwait0(){ asm volatile("cp.async.wait_group 0;\n"); }

__device__ __forceinline__ unsigned scvt(const void* p){
    return (unsigned)__cvta_generic_to_shared(p);
}
__device__ __forceinline__ void ldsm4(unsigned &r0, unsigned &r1, unsigned &r2, unsigned &r3,
                                      unsigned saddr){
    asm volatile("ldmatrix.sync.aligned.m8n8.x4.shared.b16 {%0,%1,%2,%3}, [%4];"
        : "=r"(r0), "=r"(r1), "=r"(r2), "=r"(r3) : "r"(saddr));
}
__device__ __forceinline__ void ldsm4t(unsigned &r0, unsigned &r1, unsigned &r2, unsigned &r3,
                                       unsigned saddr){
    asm volatile("ldmatrix.sync.aligned.m8n8.x4.trans.shared.b16 {%0,%1,%2,%3}, [%4];"
        : "=r"(r0), "=r"(r1), "=r"(r2), "=r"(r3) : "r"(saddr));
}

__device__ __forceinline__ void mma16816(float* c, const unsigned* a, const unsigned* b){
    asm volatile(
        "mma.sync.aligned.m16n8k16.row.col.f32.bf16.bf16.f32 "
        "{%0,%1,%2,%3}, {%4,%5,%6,%7}, {%8,%9}, {%0,%1,%2,%3};"
        : "+f"(c[0]), "+f"(c[1]), "+f"(c[2]), "+f"(c[3])
        : "r"(a[0]), "r"(a[1]), "r"(a[2]), "r"(a[3]), "r"(b[0]), "r"(b[1]));
}

/* ---------------- fused: F (fp32 + hi/lo), X hi/lo, avg, max, Bm in ONE pass ---------------- */
__global__ void k_Fused(const float* __restrict__ x, const float* __restrict__ w_f,
                        const float* __restrict__ w_a2b){
    __shared__ float wfs[KK*CC];
    __shared__ float wa[CC];
    int tid = threadIdx.x;
    for (int i = tid; i < KK*CC; i += 256) wfs[i] = w_f[i];
    for (int i = tid; i < CC; i += 256)    wa[i]  = w_a2b[i];
    __syncthreads();
    int b = blockIdx.y;
    int n = blockIdx.x*256 + tid;
    float acc[KK];
    #pragma unroll
    for (int k=0;k<KK;k++) acc[k]=0.f;
    float s=0.f, mx=-1e30f, bm=0.f;
    const float* xb = x + (size_t)b*CC*NN + n;
    for (int c=0;c<CC;c++){
        float xv = xb[(size_t)c*NN];
        s += xv; mx = fmaxf(mx, xv); bm += wa[c]*xv;
        bf16 h,l; split_bf(xv,h,l);
        size_t xi = ((size_t)b*CC+c)*NN + n;
        gXh[xi]=h; gXl[xi]=l;
        #pragma unroll
        for (int k=0;k<KK;k++) acc[k] += wfs[k*CC+c]*xv;
    }
    #pragma unroll
    for (int k=0;k<KK;k++){
        size_t idx = ((size_t)b*KK+k)*NN + n;
        gF[idx] = acc[k];
        bf16 h,l; split_bf(acc[k],h,l);
        gFh[idx]=h; gFl[idx]=l;
    }
    gAvg[b*NN+n]=s*(1.f/CC);
    gMax[b*NN+n]=mx;
    gBm [b*NN+n]=lrelu_f(bm);
}

/* ---------------- L[b,k,c] = sum_n F[b,k,n] * x[b,c,n] ---------------- */
__global__ void k_L(const float* __restrict__ x){
    int c = blockIdx.x, b = blockIdx.y, tid = threadIdx.x;
    float acc[KK];
    #pragma unroll
    for (int k=0;k<KK;k++) acc[k]=0.f;
    const float* xr = x + ((size_t)b*CC + c)*NN;
    const float* Fb = gF + (size_t)b*KK*NN;
    for (int n=tid; n<NN; n+=256){
        float xv = xr[n];
        #pragma unroll
        for (int k=0;k<KK;k++) acc[k] += Fb[(size_t)k*NN+n]*xv;
    }
    #pragma unroll
    for (int off=16; off; off>>=1){
        #pragma unroll
        for (int k=0;k<KK;k++) acc[k] += __shfl_down_sync(0xffffffffu, acc[k], off);
    }
    __shared__ float red[KK][8];
    int lane = tid & 31, wp = tid >> 5;
    if (lane == 0){
        #pragma unroll
        for (int k=0;k<KK;k++) red[k][wp] = acc[k];
    }
    __syncthreads();
    if (tid < KK){
        float s = 0.f;
        #pragma unroll
        for (int w=0;w<8;w++) s += red[tid][w];
        gL[((size_t)b*KK+tid)*CC + c] = s;
    }
}

/* ---------------- softmax over c ---------------- */
__global__ void k_softS(){
    int k = blockIdx.x, b = blockIdx.y, c = threadIdx.x;
    int lane = c & 31, wp = c >> 5;
    __shared__ float sm[8];
    float v = gL[((size_t)b*KK+k)*CC + c];
    float m = v;
    #pragma unroll
    for (int off=16; off; off>>=1) m = fmaxf(m, __shfl_xor_sync(0xffffffffu, m, off));
    if (lane == 0) sm[wp] = m;
    __syncthreads();
    m = sm[0];
    #pragma unroll
    for (int i=1;i<8;i++) m = fmaxf(m, sm[i]);
    float e = expf(v - m);
    float s = e;
    #pragma unroll
    for (int off=16; off; off>>=1) s += __shfl_xor_sync(0xffffffffu, s, off);
    __syncthreads();
    if (lane == 0) sm[wp] = s;
    __syncthreads();
    s = 0.f;
    #pragma unroll
    for (int i=0;i<8;i++) s += sm[i];
    gS[((size_t)b*KK+k)*CC + c] = e / s;
}

/* ---------------- folded weights into gWHh (segments Esp, x) + gWb ---------------- */
__global__ void k_prepW(const float* __restrict__ w_h, const float* __restrict__ w_beta,
                        const float* __restrict__ w_e){
    __shared__ float whr[2*CC];
    int o = blockIdx.x, tid = threadIdx.x;
    whr[tid]     = w_h[(size_t)o*2*CC + tid];
    whr[tid+CC]  = w_h[(size_t)o*2*CC + CC + tid];
    __syncthreads();
    int c = tid;
    float a1 = 0.f, a2 = 0.f;
    for (int j=0;j<CC;j++){
        a1 += whr[j]    * w_beta[j*CC + c];
        a2 += whr[CC+j] * w_e   [j*CC + c];
    }
    gWb[o*CC + c] = a1;
    float wx = whr[c] + whr[CC+c];
    bf16 h2,l2,hx,lx;
    split_bf(a2,h2,l2); split_bf(wx,hx,lx);
    for (int b=0;b<BB;b++){
        size_t base = ((size_t)b*CC + o)*KHH;
        gWHhH[base + 16  + c] = h2; gWHhL[base + 16  + c] = l2;
        gWHhH[base + 272 + c] = hx; gWHhL[base + 272 + c] = lx;
    }
}

/* ---------------- per-batch W_EF segment: gWHh[b][o][k<16] ---------------- */
__global__ void k_prepWef(){
    int o = blockIdx.x, b = blockIdx.y, tid = threadIdx.x;  /* 128 threads */
    float acc[KK];
    #pragma unroll
    for (int k=0;k<KK;k++) acc[k]=0.f;
    for (int c=tid; c<CC; c+=128){
        float wv = gWb[o*CC + c];
        #pragma unroll
        for (int k=0;k<KK;k++) acc[k] += wv * gS[((size_t)b*KK+k)*CC + c];
    }
    #pragma unroll
    for (int off=16; off; off>>=1){
        #pragma unroll
        for (int k=0;k<KK;k++) acc[k] += __shfl_down_sync(0xffffffffu, acc[k], off);
    }
    __shared__ float red[KK][4];
    int lane = tid & 31, wp = tid >> 5;
    if (lane == 0){
        #pragma unroll
        for (int k=0;k<KK;k++) red[k][wp] = acc[k];
    }
    __syncthreads();
    if (tid < KK){
        float s = red[tid][0]+red[tid][1]+red[tid][2]+red[tid][3];
        bf16 h,l; split_bf(s,h,l);
        size_t base = ((size_t)b*CC + o)*KHH;
        gWHhH[base + tid] = h;
        gWHhL[base + tid] = l;
    }
}

/* ---------------- convert 256x512 fp32 weight -> bf16 hi/lo (same layout) ---------------- */
__global__ void k_convW(const float* __restrict__ w, bf16* __restrict__ wh, bf16* __restrict__ wl){
    int i = blockIdx.x*256 + threadIdx.x;
    bf16 h,l; split_bf(w[i],h,l);
    wh[i]=h; wl[i]=l;
}

/* ---------------- avg/max convs 1/3/5/7 -> F4, Cm ---------------- */
__global__ void k_F4Cm(const float* __restrict__ w1, const float* __restrict__ w3,
                       const float* __restrict__ w5, const float* __restrict__ w7,
                       const float* __restrict__ wf2c){
    __shared__ float s1w[2], s3w[18], s5w[50], s7w[98], c4[4];
    int tid = threadIdx.x;
    if (tid < 2)  s1w[tid]=w1[tid];
    if (tid < 18) s3w[tid]=w3[tid];
    if (tid < 50) s5w[tid]=w5[tid];
    if (tid < 98) s7w[tid]=w7[tid];
    if (tid < 4)  c4[tid]=wf2c[tid];
    __syncthreads();
    int b = blockIdx.y, n = blockIdx.x*256 + tid;
    int h = n / WW, w = n - h*WW;
    const float* av  = gAvg + b*NN;
    const float* mxp = gMax + b*NN;
    float s1=0.f, s3=0.f, s5=0.f, s7=0.f;
    #pragma unroll
    for (int dy=-3; dy<=3; dy++){
        int y = h+dy; if (y<0 || y>=HH) continue;
        #pragma unroll
        for (int dx=-3; dx<=3; dx++){
            int x2 = w+dx; if (x2<0 || x2>=WW) continue;
            float a = av[y*WW+x2], m = mxp[y*WW+x2];
            s7 += a*s7w[(dy+3)*7+dx+3] + m*s7w[49+(dy+3)*7+dx+3];
            if (dy>=-2 && dy<=2 && dx>=-2 && dx<=2)
                s5 += a*s5w[(dy+2)*5+dx+2] + m*s5w[25+(dy+2)*5+dx+2];
            if (dy>=-1 && dy<=1 && dx>=-1 && dx<=1)
                s3 += a*s3w[(dy+1)*3+dx+1] + m*s3w[9+(dy+1)*3+dx+1];
            if (dy==0 && dx==0)
                s1 = a*s1w[0] + m*s1w[1];
        }
    }
    float f0=lrelu_f(s1), f1=lrelu_f(s3), f2=lrelu_f(s5), f3=lrelu_f(s7);
    gF4[((size_t)b*4+0)*NN+n]=f0;
    gF4[((size_t)b*4+1)*NN+n]=f1;
    gF4[((size_t)b*4+2)*NN+n]=f2;
    gF4[((size_t)b*4+3)*NN+n]=f3;
    gCm[b*NN+n] = lrelu_f(c4[0]*f0 + c4[1]*f1 + c4[2]*f2 + c4[3]*f3);
}

/* ---------------- Ssp ---------------- */
__global__ void k_Ssp(){
    int h = blockIdx.x, b = blockIdx.y, tid = threadIdx.x;
    __shared__ float sm[4];
    float lg = -1e30f;
    if (tid < HH){
        float a = 0.f;
        const float* bm = gBm + b*NN + h*WW;
        const float* cm = gCm + b*NN;
        for (int w=0; w<WW; w++) a += bm[w]*cm[w*HH + tid];
        lg = a;
    }
    int lane = tid & 31, wp = tid >> 5;
    float m = lg;
    #pragma unroll
    for (int off=16; off; off>>=1) m = fmaxf(m, __shfl_xor_sync(0xffffffffu, m, off));
    if (lane == 0) sm[wp] = m;
    __syncthreads();
    m = fmaxf(fmaxf(sm[0],sm[1]), fmaxf(sm[2],sm[3]));
    float e = (tid < HH) ? expf(lg - m) : 0.f;
    float s = e;
    #pragma unroll
    for (int off=16; off; off>>=1) s += __shfl_xor_sync(0xffffffffu, s, off);
    __syncthreads();
    if (lane == 0) sm[wp] = s;
    __syncthreads();
    s = sm[0]+sm[1]+sm[2]+sm[3];
    if (tid < HH) gSsp[((size_t)b*HH + h)*HH + tid] = e / s;
}

/* ---------------- Esp -> bf16 hi/lo ---------------- */
__global__ void k_Esp(const float* __restrict__ w_f2d){
    extern __shared__ float sh[];
    float* sS = sh;
    float* sD = sh + NN;
    int c = blockIdx.x, b = blockIdx.y, tid = threadIdx.x;
    float d0=w_f2d[c*4+0], d1=w_f2d[c*4+1], d2=w_f2d[c*4+2], d3=w_f2d[c*4+3];
    const float* f4b = gF4 + (size_t)b*4*NN;
    const float* ssp = gSsp + (size_t)b*NN;
    for (int i=tid; i<NN; i+=288){
        sS[i] = ssp[i];
        float v = d0*f4b[i] + d1*f4b[NN+i] + d2*f4b[2*NN+i] + d3*f4b[3*NN+i];
        sD[i] = lrelu_f(v);
    }
    __syncthreads();
    int w = tid % 96, hb = tid / 96;
    float acc[32];
    #pragma unroll
    for (int r=0;r<32;r++) acc[r]=0.f;
    for (int k=0;k<96;k++){
        float dl = sD[k*96 + w];
        #pragma unroll
        for (int r=0;r<32;r++) acc[r] += sS[(hb+3*r)*96 + k]*dl;
    }
    size_t base = ((size_t)b*CC + c)*NN;
    #pragma unroll
    for (int r=0;r<32;r++){
        bf16 h,l; split_bf(acc[r],h,l);
        size_t idx = base + (hb+3*r)*96 + w;
        gEh[idx]=h; gEl[idx]=l;
    }
}

/* ---------------- tensor-core GEMM, bf16x3, M=256 x N=64 CTA tile (B read ONCE) ----------------
   out[b,o,n] = act( sum_k W[o][k] * B[k][b,n] ), B = [seg0;seg1;seg2] (hi/lo pairs)
   A (weights) [o][KTOT] k-contiguous bf16 hi/lo; PERB: per-batch A.
   Dynamic smem: sAh[2][256][24], sAl, sBh[2][16][72], sBl = 58368 bytes. */
#define TG_APITCH 24
#define TG_BPITCH 72
#define TG_SMA (256*TG_APITCH)   /* per buffer: 6144 elems */
#define TG_SMB (16*TG_BPITCH)    /* per buffer: 1152 elems */
#define TG_SMEM_BYTES ((2*TG_SMA*2 + 2*TG_SMB*2) * 2)   /* 58368 */

template<int ACT, int OUTPAIR, int KTOT, int PERB, int S0, int S1, int S2>
__global__ __launch_bounds__(256) void tcgemm(
    const bf16* __restrict__ Wh, const bf16* __restrict__ Wl,
    const bf16* __restrict__ p0h, const bf16* __restrict__ p0l,
    const bf16* __restrict__ p1h, const bf16* __restrict__ p1l,
    const bf16* __restrict__ p2h, const bf16* __restrict__ p2l,
    float* __restrict__ outf, bf16* __restrict__ outh, bf16* __restrict__ outl)
{
    constexpr int NT = KTOT/16;
    extern __shared__ bf16 dsm[];
    bf16* sAh = dsm;                    /* [2][256][24] */
    bf16* sAl = sAh + 2*TG_SMA;
    bf16* sBh = sAl + 2*TG_SMA;         /* [2][16][72]  */
    bf16* sBl = sBh + 2*TG_SMB;

    int tid = threadIdx.x;
    int j0 = blockIdx.x * 64;
    int b  = j0 / NN;
    int n0 = j0 - b*NN;
    int lane = tid & 31, w = tid >> 5;
    int wm = (w >> 1) * 64, wn = (w & 1) * 32;
    int g = lane >> 2, t4 = lane & 3;
    int ra = lane & 15, ca = (lane >> 4) * 8;

    float acc[4][4][4];
    #pragma unroll
    for (int mi=0;mi<4;mi++)
        #pragma unroll
        for (int ni=0;ni<4;ni++)
            #pragma unroll
            for (int r=0;r<4;r++) acc[mi][ni][r]=0.f;

    const bf16* WhB = Wh + (PERB ? (size_t)b*CC*KTOT : 0);
    const bf16* WlB = Wl + (PERB ? (size_t)b*CC*KTOT : 0);

    auto fill = [&](int kt, int bufi){
        /* A: 256 rows x 16 k, hi+lo; 16B chunks: 1024 total, 4/thread */
        #pragma unroll
        for (int i = tid; i < 1024; i += 256){
            int arr = i >> 9, r = i & 511, o = r >> 1, half = r & 1;
            const bf16* src = (arr ? WlB : WhB) + (size_t)o*KTOT + kt + half*8;
            bf16* dst = (arr ? sAl : sAh) + bufi*TG_SMA + o*TG_APITCH + half*8;
            cpasync16(scvt(dst), src);
        }
        /* B: 16 rows x 64 n, hi+lo; 16B chunks: 256 total, 1/thread */
        {
            int i = tid;
            int arr = i >> 7, r = i & 127, k = r >> 3, ch = r & 7;
            int kg = kt + k;
            const bf16 *ph, *pl; int kr, S;
            if (kg < S0){ ph=p0h; pl=p0l; kr=kg; S=S0; }
            else if (kg < S0+S1){ ph=p1h; pl=p1l; kr=kg-S0; S=S1; }
            else { ph=p2h; pl=p2l; kr=kg-S0-S1; S=(S2>0?S2:1); }
            const bf16* src = (arr ? pl : ph) + ((size_t)b*S + kr)*NN + n0 + ch*8;
            bf16* dst = (arr ? sBl : sBh) + bufi*TG_SMB + k*TG_BPITCH + ch*8;
            cpasync16(scvt(dst), src);
        }
    };

    fill(0, 0);
    cpcommit();
    int buf = 0;
    #pragma unroll 1
    for (int step = 0; step < NT; step++){
        cpwait0();
        __syncthreads();
        if (step + 1 < NT){
            fill((step+1)*16, buf^1);
            cpcommit();
        }
        const bf16* Ah = sAh + buf*TG_SMA;
        const bf16* Al = sAl + buf*TG_SMA;
        const bf16* Bh = sBh + buf*TG_SMB;
        const bf16* Bl = sBl + buf*TG_SMB;
        /* fragment loads via ldmatrix */
        unsigned ah[4][4], al[4][4], bh[4][2], bl[4][2];
        #pragma unroll
        for (int mi=0;mi<4;mi++){
            ldsm4(ah[mi][0],ah[mi][1],ah[mi][2],ah[mi][3],
                  scvt(&Ah[(wm + mi*16 + ra)*TG_APITCH + ca]));
            ldsm4(al[mi][0],al[mi][1],al[mi][2],al[mi][3],
                  scvt(&Al[(wm + mi*16 + ra)*TG_APITCH + ca]));
        }
        #pragma unroll
        for (int nb=0; nb<2; nb++){
            ldsm4t(bh[2*nb][0],bh[2*nb][1],bh[2*nb+1][0],bh[2*nb+1][1],
                   scvt(&Bh[ra*TG_BPITCH + wn + nb*16 + ca]));
            ldsm4t(bl[2*nb][0],bl[2*nb][1],bl[2*nb+1][0],bl[2*nb+1][1],
                   scvt(&Bl[ra*TG_BPITCH + wn + nb*16 + ca]));
        }
        #pragma unroll
        for (int mi=0;mi<4;mi++)
            #pragma unroll
            for (int ni=0;ni<4;ni++){
                mma16816(acc[mi][ni], ah[mi], bh[ni]);
                mma16816(acc[mi][ni], al[mi], bh[ni]);
                mma16816(acc[mi][ni], ah[mi], bl[ni]);
            }
        __syncthreads();
        buf ^= 1;
    }

    /* epilogue */
    #pragma unroll
    for (int mi=0;mi<4;mi++){
        int oa = wm + mi*16 + g;
        #pragma unroll
        for (int ni=0;ni<4;ni++){
            int n = n0 + wn + ni*8 + 2*t4;
            float v0=acc[mi][ni][0], v1=acc[mi][ni][1], v2=acc[mi][ni][2], v3=acc[mi][ni][3];
            if (ACT==1){ v0=lrelu_f(v0); v1=lrelu_f(v1); v2=lrelu_f(v2); v3=lrelu_f(v3); }
            if (ACT==2){
                v0=1.f/(1.f+expf(-v0)); v1=1.f/(1.f+expf(-v1));
                v2=1.f/(1.f+expf(-v2)); v3=1.f/(1.f+expf(-v3));
            }
            size_t i0 = ((size_t)b*CC + oa    )*NN + n;
            size_t i1 = ((size_t)b*CC + oa + 8)*NN + n;
            if (OUTPAIR){
                bf16 h0,l0,h1,l1;
                split_bf(v0,h0,l0); split_bf(v1,h1,l1);
                *(unsigned*)&outh[i0] = (unsigned)__bfloat16_as_ushort(h0) | ((unsigned)__bfloat16_as_ushort(h1)<<16);
                *(unsigned*)&outl[i0] = (unsigned)__bfloat16_as_ushort(l0) | ((unsigned)__bfloat16_as_ushort(l1)<<16);
                split_bf(v2,h0,l0); split_bf(v3,h1,l1);
                *(unsigned*)&outh[i1] = (unsigned)__bfloat16_as_ushort(h0) | ((unsigned)__bfloat16_as_ushort(h1)<<16);
                *(unsigned*)&outl[i1] = (unsigned)__bfloat16_as_ushort(l0) | ((unsigned)__bfloat16_as_ushort(l1)<<16);
            } else {
                float2 u; u.x=v0; u.y=v1; *(float2*)&outf[i0] = u;
                u.x=v2; u.y=v3;           *(float2*)&outf[i1] = u;
            }
        }
    }
}

/* ---------------- launch ---------------- */
extern "C" void kernel_launch(void* const* d_in, const int* in_sizes, int n_in,
                              void* d_out, int out_size)
{
    const float* x      = (const float*)d_in[0];
    const float* w_f    = (const float*)d_in[1];
    const float* w_beta = (const float*)d_in[2];
    const float* w1     = (const float*)d_in[3];
    const float* w3     = (const float*)d_in[4];
    const float* w5     = (const float*)d_in[5];
    const float* w7     = (const float*)d_in[6];
    const float* w_a2b  = (const float*)d_in[7];
    const float* w_f2c  = (const float*)d_in[8];
    const float* w_f2d  = (const float*)d_in[9];
    const float* w_e    = (const float*)d_in[10];
    const float* w_h    = (const float*)d_in[11];
    const float* w_m    = (const float*)d_in[12];
    const float* w_hm   = (const float*)d_in[13];
    float* out = (float*)d_out;

    bf16 *pFh,*pFl,*pEh,*pEl,*pXh,*pXl,*pHhh,*pHhl,*pMh,*pMl;
    bf16 *pWHhH,*pWHhL,*pWMH,*pWML,*pWHMH,*pWHML;
    cudaGetSymbolAddress((void**)&pFh,  gFh);   cudaGetSymbolAddress((void**)&pFl,  gFl);
    cudaGetSymbolAddress((void**)&pEh,  gEh);   cudaGetSymbolAddress((void**)&pEl,  gEl);
    cudaGetSymbolAddress((void**)&pXh,  gXh);   cudaGetSymbolAddress((void**)&pXl,  gXl);
    cudaGetSymbolAddress((void**)&pHhh, gHhh);  cudaGetSymbolAddress((void**)&pHhl, gHhl);
    cudaGetSymbolAddress((void**)&pMh,  gMh);   cudaGetSymbolAddress((void**)&pMl,  gMl);
    cudaGetSymbolAddress((void**)&pWHhH,gWHhH); cudaGetSymbolAddress((void**)&pWHhL,gWHhL);
    cudaGetSymbolAddress((void**)&pWMH, gWMH);  cudaGetSymbolAddress((void**)&pWML, gWML);
    cudaGetSymbolAddress((void**)&pWHMH,gWHMH); cudaGetSymbolAddress((void**)&pWHML,gWHML);

    cudaFuncSetAttribute(k_Esp, cudaFuncAttributeMaxDynamicSharedMemorySize, 2*NN*sizeof(float));
    cudaFuncSetAttribute((const void*)tcgemm<1,1,KHH,1, 16,256,256>,
                         cudaFuncAttributeMaxDynamicSharedMemorySize, TG_SMEM_BYTES);
    cudaFuncSetAttribute((const void*)tcgemm<2,1,512,0, 256,256,0>,
                         cudaFuncAttributeMaxDynamicSharedMemorySize, TG_SMEM_BYTES);
    cudaFuncSetAttribute((const void*)tcgemm<1,0,512,0, 256,256,0>,
                         cudaFuncAttributeMaxDynamicSharedMemorySize, TG_SMEM_BYTES);

    dim3 gtile(BNT/64);

    /* weight prep */
    k_prepW <<<CC, 256>>>(w_h, w_beta, w_e);
    k_convW <<<CC*2*CC/256, 256>>>(w_m,  pWMH,  pWML);
    k_convW <<<CC*2*CC/256, 256>>>(w_hm, pWHMH, pWHML);

    /* channel-attention path (also emits Xh/Xl, Fh/Fl) */
    k_Fused<<<dim3(NN/256, BB), 256>>>(x, w_f, w_a2b);
    k_L    <<<dim3(CC, BB),     256>>>(x);
    k_softS<<<dim3(KK, BB),     256>>>();
    k_prepWef<<<dim3(CC, BB),   128>>>();

    /* spatial-attention path */
    k_F4Cm<<<dim3(NN/256, BB), 256>>>(w1, w3, w5, w7, w_f2c);
    k_Ssp <<<dim3(HH, BB), 128>>>();
    k_Esp <<<dim3(CC, BB), 288, 2*NN*sizeof(float)>>>(w_f2d);

    /* tensor-core head: Hh, M, H_M (M=256 tiles, B read once) */
    tcgemm<1,1,KHH,1, 16,256,256><<<gtile,256,TG_SMEM_BYTES>>>(pWHhH,pWHhL, pFh,pFl, pEh,pEl, pXh,pXl,
                                                 (float*)0, pHhh, pHhl);
    tcgemm<2,1,512,0, 256,256,0><<<gtile,256,TG_SMEM_BYTES>>>(pWMH,pWML,  pHhh,pHhl, pXh,pXl, pXh,pXl,
                                                 (float*)0, pMh, pMl);
    tcgemm<1,0,512,0, 256,256,0><<<gtile,256,TG_SMEM_BYTES>>>(pWHMH,pWHML, pHhh,pHhl, pMh,pMl, pMh,pMl,
                                                 out, (bf16*)0, (bf16*)0);
}

// round 14
// speedup vs baseline: 1.0794x; 1.0794x over previous
#include <cuda_runtime.h>
#include <cuda_bf16.h>
#include <cstdint>

#define BB 8
#define CC 256
#define HH 96
#define WW 96
#define NN (HH*WW)        /* 9216 */
#define KK 16
#define BNT (BB*NN)       /* 73728 */
#define KHH 528           /* 16 + 256 + 256 */

typedef __nv_bfloat16 bf16;

/* ---------------- scratch (device globals) ---------------- */
__device__ float gF   [BB*KK*NN];     /* fp32 F for k_L */
__device__ float gL   [BB*KK*CC];
__device__ float gS   [BB*KK*CC];
__device__ float gAvg [BB*NN];
__device__ float gMax [BB*NN];
__device__ float gBm  [BB*NN];
__device__ float gF4  [BB*4*NN];
__device__ float gCm  [BB*NN];
__device__ float gSsp [BB*HH*HH];
__device__ float gWb  [CC*CC];        /* Wb' = w_h1 . w_beta (fp32, feeds prepWef) */

/* bf16 hi/lo operand arrays, layout [b][k][n] (n contiguous) */
__device__ bf16 gFh [BB*KK*NN],  gFl [BB*KK*NN];
__device__ bf16 gEh [BB*CC*NN],  gEl [BB*CC*NN];   /* Esp */
__device__ bf16 gXh [BB*CC*NN],  gXl [BB*CC*NN];   /* x   */
__device__ bf16 gHhh[BB*CC*NN],  gHhl[BB*CC*NN];   /* Hh  */
__device__ bf16 gMh [BB*CC*NN],  gMl [BB*CC*NN];   /* M   */

/* bf16 hi/lo weights, layout [o][K] (K contiguous) */
__device__ bf16 gWHhH[BB*CC*KHH], gWHhL[BB*CC*KHH];  /* per-batch [b][o][528] */
__device__ bf16 gWMH [CC*2*CC],   gWML [CC*2*CC];
__device__ bf16 gWHMH[CC*2*CC],   gWHML[CC*2*CC];

__device__ __forceinline__ float lrelu_f(float v){ return v >= 0.f ? v : 0.001f*v; }

__device__ __forceinline__ void split_bf(float v, bf16& h, bf16& l){
    h = __float2bfloat16_rn(v);
    l = __float2bfloat16_rn(v - __bfloat162float(h));
}

__device__ __forceinline__ void cpasync16(unsigned int saddr, const void* g){
    asm volatile("cp.async.ca.shared.global [%0], [%1], 16;\n" :: "r"(saddr), "l"(g));
}
__device__ __forceinline__ void cpcommit(){ asm volatile("cp.async.commit_group;\n"); }
__device__ __forceinline__ void cpwait1(){ asm volatile("cp.async.wait_group 1;\n"); }

__device__ __forceinline__ unsigned scvt(const void* p){
    return (unsigned)__cvta_generic_to_shared(p);
}
__device__ __forceinline__ void ldsm4(unsigned &r0, unsigned &r1, unsigned &r2, unsigned &r3,
                                      unsigned saddr){
    asm volatile("ldmatrix.sync.aligned.m8n8.x4.shared.b16 {%0,%1,%2,%3}, [%4];"
        : "=r"(r0), "=r"(r1), "=r"(r2), "=r"(r3) : "r"(saddr));
}
__device__ __forceinline__ void ldsm4t(unsigned &r0, unsigned &r1, unsigned &r2, unsigned &r3,
                                       unsigned saddr){
    asm volatile("ldmatrix.sync.aligned.m8n8.x4.trans.shared.b16 {%0,%1,%2,%3}, [%4];"
        : "=r"(r0), "=r"(r1), "=r"(r2), "=r"(r3) : "r"(saddr));
}

__device__ __forceinline__ void mma16816(float* c, const unsigned* a, const unsigned* b){
    asm volatile(
        "mma.sync.aligned.m16n8k16.row.col.f32.bf16.bf16.f32 "
        "{%0,%1,%2,%3}, {%4,%5,%6,%7}, {%8,%9}, {%0,%1,%2,%3};"
        : "+f"(c[0]), "+f"(c[1]), "+f"(c[2]), "+f"(c[3])
        : "r"(a[0]), "r"(a[1]), "r"(a[2]), "r"(a[3]), "r"(b[0]), "r"(b[1]));
}

/* ---------------- fused: F (fp32 + hi/lo), X hi/lo, avg, max, Bm in ONE pass ---------------- */
__global__ void k_Fused(const float* __restrict__ x, const float* __restrict__ w_f,
                        const float* __restrict__ w_a2b){
    __shared__ float wfs[KK*CC];
    __shared__ float wa[CC];
    int tid = threadIdx.x;
    for (int i = tid; i < KK*CC; i += 256) wfs[i] = w_f[i];
    for (int i = tid; i < CC; i += 256)    wa[i]  = w_a2b[i];
    __syncthreads();
    int b = blockIdx.y;
    int n = blockIdx.x*256 + tid;
    float acc[KK];
    #pragma unroll
    for (int k=0;k<KK;k++) acc[k]=0.f;
    float s=0.f, mx=-1e30f, bm=0.f;
    const float* xb = x + (size_t)b*CC*NN + n;
    for (int c=0;c<CC;c++){
        float xv = xb[(size_t)c*NN];
        s += xv; mx = fmaxf(mx, xv); bm += wa[c]*xv;
        bf16 h,l; split_bf(xv,h,l);
        size_t xi = ((size_t)b*CC+c)*NN + n;
        gXh[xi]=h; gXl[xi]=l;
        #pragma unroll
        for (int k=0;k<KK;k++) acc[k] += wfs[k*CC+c]*xv;
    }
    #pragma unroll
    for (int k=0;k<KK;k++){
        size_t idx = ((size_t)b*KK+k)*NN + n;
        gF[idx] = acc[k];
        bf16 h,l; split_bf(acc[k],h,l);
        gFh[idx]=h; gFl[idx]=l;
    }
    gAvg[b*NN+n]=s*(1.f/CC);
    gMax[b*NN+n]=mx;
    gBm [b*NN+n]=lrelu_f(bm);
}

/* ---------------- L[b,k,c] = sum_n F[b,k,n] * x[b,c,n] ---------------- */
__global__ void k_L(const float* __restrict__ x){
    int c = blockIdx.x, b = blockIdx.y, tid = threadIdx.x;
    float acc[KK];
    #pragma unroll
    for (int k=0;k<KK;k++) acc[k]=0.f;
    const float* xr = x + ((size_t)b*CC + c)*NN;
    const float* Fb = gF + (size_t)b*KK*NN;
    for (int n=tid; n<NN; n+=256){
        float xv = xr[n];
        #pragma unroll
        for (int k=0;k<KK;k++) acc[k] += Fb[(size_t)k*NN+n]*xv;
    }
    #pragma unroll
    for (int off=16; off; off>>=1){
        #pragma unroll
        for (int k=0;k<KK;k++) acc[k] += __shfl_down_sync(0xffffffffu, acc[k], off);
    }
    __shared__ float red[KK][8];
    int lane = tid & 31, wp = tid >> 5;
    if (lane == 0){
        #pragma unroll
        for (int k=0;k<KK;k++) red[k][wp] = acc[k];
    }
    __syncthreads();
    if (tid < KK){
        float s = 0.f;
        #pragma unroll
        for (int w=0;w<8;w++) s += red[tid][w];
        gL[((size_t)b*KK+tid)*CC + c] = s;
    }
}

/* ---------------- softmax over c ---------------- */
__global__ void k_softS(){
    int k = blockIdx.x, b = blockIdx.y, c = threadIdx.x;
    int lane = c & 31, wp = c >> 5;
    __shared__ float sm[8];
    float v = gL[((size_t)b*KK+k)*CC + c];
    float m = v;
    #pragma unroll
    for (int off=16; off; off>>=1) m = fmaxf(m, __shfl_xor_sync(0xffffffffu, m, off));
    if (lane == 0) sm[wp] = m;
    __syncthreads();
    m = sm[0];
    #pragma unroll
    for (int i=1;i<8;i++) m = fmaxf(m, sm[i]);
    float e = expf(v - m);
    float s = e;
    #pragma unroll
    for (int off=16; off; off>>=1) s += __shfl_xor_sync(0xffffffffu, s, off);
    __syncthreads();
    if (lane == 0) sm[wp] = s;
    __syncthreads();
    s = 0.f;
    #pragma unroll
    for (int i=0;i<8;i++) s += sm[i];
    gS[((size_t)b*KK+k)*CC + c] = e / s;
}

/* ---------------- folded weights into gWHh (segments Esp, x) + gWb ---------------- */
__global__ void k_prepW(const float* __restrict__ w_h, const float* __restrict__ w_beta,
                        const float* __restrict__ w_e){
    __shared__ float whr[2*CC];
    int o = blockIdx.x, tid = threadIdx.x;
    whr[tid]     = w_h[(size_t)o*2*CC + tid];
    whr[tid+CC]  = w_h[(size_t)o*2*CC + CC + tid];
    __syncthreads();
    int c = tid;
    float a1 = 0.f, a2 = 0.f;
    for (int j=0;j<CC;j++){
        a1 += whr[j]    * w_beta[j*CC + c];
        a2 += whr[CC+j] * w_e   [j*CC + c];
    }
    gWb[o*CC + c] = a1;
    float wx = whr[c] + whr[CC+c];
    bf16 h2,l2,hx,lx;
    split_bf(a2,h2,l2); split_bf(wx,hx,lx);
    for (int b=0;b<BB;b++){
        size_t base = ((size_t)b*CC + o)*KHH;
        gWHhH[base + 16  + c] = h2; gWHhL[base + 16  + c] = l2;
        gWHhH[base + 272 + c] = hx; gWHhL[base + 272 + c] = lx;
    }
}

/* ---------------- per-batch W_EF segment: gWHh[b][o][k<16] ---------------- */
__global__ void k_prepWef(){
    int o = blockIdx.x, b = blockIdx.y, tid = threadIdx.x;  /* 128 threads */
    float acc[KK];
    #pragma unroll
    for (int k=0;k<KK;k++) acc[k]=0.f;
    for (int c=tid; c<CC; c+=128){
        float wv = gWb[o*CC + c];
        #pragma unroll
        for (int k=0;k<KK;k++) acc[k] += wv * gS[((size_t)b*KK+k)*CC + c];
    }
    #pragma unroll
    for (int off=16; off; off>>=1){
        #pragma unroll
        for (int k=0;k<KK;k++) acc[k] += __shfl_down_sync(0xffffffffu, acc[k], off);
    }
    __shared__ float red[KK][4];
    int lane = tid & 31, wp = tid >> 5;
    if (lane == 0){
        #pragma unroll
        for (int k=0;k<KK;k++) red[k][wp] = acc[k];
    }
    __syncthreads();
    if (tid < KK){
        float s = red[tid][0]+red[tid][1]+red[tid][2]+red[tid][3];
        bf16 h,l; split_bf(s,h,l);
        size_t base = ((size_t)b*CC + o)*KHH;
        gWHhH[base + tid] = h;
        gWHhL[base + tid] = l;
    }
}

/* ---------------- convert 256x512 fp32 weight -> bf16 hi/lo (same layout) ---------------- */
__global__ void k_convW(const float* __restrict__ w, bf16* __restrict__ wh, bf16* __restrict__ wl){
    int i = blockIdx.x*256 + threadIdx.x;
    bf16 h,l; split_bf(w[i],h,l);
    wh[i]=h; wl[i]=l;
}

/* ---------------- avg/max convs 1/3/5/7 -> F4, Cm ---------------- */
__global__ void k_F4Cm(const float* __restrict__ w1, const float* __restrict__ w3,
                       const float* __restrict__ w5, const float* __restrict__ w7,
                       const float* __restrict__ wf2c){
    __shared__ float s1w[2], s3w[18], s5w[50], s7w[98], c4[4];
    int tid = threadIdx.x;
    if (tid < 2)  s1w[tid]=w1[tid];
    if (tid < 18) s3w[tid]=w3[tid];
    if (tid < 50) s5w[tid]=w5[tid];
    if (tid < 98) s7w[tid]=w7[tid];
    if (tid < 4)  c4[tid]=wf2c[tid];
    __syncthreads();
    int b = blockIdx.y, n = blockIdx.x*256 + tid;
    int h = n / WW, w = n - h*WW;
    const float* av  = gAvg + b*NN;
    const float* mxp = gMax + b*NN;
    float s1=0.f, s3=0.f, s5=0.f, s7=0.f;
    #pragma unroll
    for (int dy=-3; dy<=3; dy++){
        int y = h+dy; if (y<0 || y>=HH) continue;
        #pragma unroll
        for (int dx=-3; dx<=3; dx++){
            int x2 = w+dx; if (x2<0 || x2>=WW) continue;
            float a = av[y*WW+x2], m = mxp[y*WW+x2];
            s7 += a*s7w[(dy+3)*7+dx+3] + m*s7w[49+(dy+3)*7+dx+3];
            if (dy>=-2 && dy<=2 && dx>=-2 && dx<=2)
                s5 += a*s5w[(dy+2)*5+dx+2] + m*s5w[25+(dy+2)*5+dx+2];
            if (dy>=-1 && dy<=1 && dx>=-1 && dx<=1)
                s3 += a*s3w[(dy+1)*3+dx+1] + m*s3w[9+(dy+1)*3+dx+1];
            if (dy==0 && dx==0)
                s1 = a*s1w[0] + m*s1w[1];
        }
    }
    float f0=lrelu_f(s1), f1=lrelu_f(s3), f2=lrelu_f(s5), f3=lrelu_f(s7);
    gF4[((size_t)b*4+0)*NN+n]=f0;
    gF4[((size_t)b*4+1)*NN+n]=f1;
    gF4[((size_t)b*4+2)*NN+n]=f2;
    gF4[((size_t)b*4+3)*NN+n]=f3;
    gCm[b*NN+n] = lrelu_f(c4[0]*f0 + c4[1]*f1 + c4[2]*f2 + c4[3]*f3);
}

/* ---------------- Ssp ---------------- */
__global__ void k_Ssp(){
    int h = blockIdx.x, b = blockIdx.y, tid = threadIdx.x;
    __shared__ float sm[4];
    float lg = -1e30f;
    if (tid < HH){
        float a = 0.f;
        const float* bm = gBm + b*NN + h*WW;
        const float* cm = gCm + b*NN;
        for (int w=0; w<WW; w++) a += bm[w]*cm[w*HH + tid];
        lg = a;
    }
    int lane = tid & 31, wp = tid >> 5;
    float m = lg;
    #pragma unroll
    for (int off=16; off; off>>=1) m = fmaxf(m, __shfl_xor_sync(0xffffffffu, m, off));
    if (lane == 0) sm[wp] = m;
    __syncthreads();
    m = fmaxf(fmaxf(sm[0],sm[1]), fmaxf(sm[2],sm[3]));
    float e = (tid < HH) ? expf(lg - m) : 0.f;
    float s = e;
    #pragma unroll
    for (int off=16; off; off>>=1) s += __shfl_xor_sync(0xffffffffu, s, off);
    __syncthreads();
    if (lane == 0) sm[wp] = s;
    __syncthreads();
    s = sm[0]+sm[1]+sm[2]+sm[3];
    if (tid < HH) gSsp[((size_t)b*HH + h)*HH + tid] = e / s;
}

/* ---------------- Esp -> bf16 hi/lo ---------------- */
__global__ void k_Esp(const float* __restrict__ w_f2d){
    extern __shared__ float sh[];
    float* sS = sh;
    float* sD = sh + NN;
    int c = blockIdx.x, b = blockIdx.y, tid = threadIdx.x;
    float d0=w_f2d[c*4+0], d1=w_f2d[c*4+1], d2=w_f2d[c*4+2], d3=w_f2d[c*4+3];
    const float* f4b = gF4 + (size_t)b*4*NN;
    const float* ssp = gSsp + (size_t)b*NN;
    for (int i=tid; i<NN; i+=288){
        sS[i] = ssp[i];
        float v = d0*f4b[i] + d1*f4b[NN+i] + d2*f4b[2*NN+i] + d3*f4b[3*NN+i];
        sD[i] = lrelu_f(v);
    }
    __syncthreads();
    int w = tid % 96, hb = tid / 96;
    float acc[32];
    #pragma unroll
    for (int r=0;r<32;r++) acc[r]=0.f;
    for (int k=0;k<96;k++){
        float dl = sD[k*96 + w];
        #pragma unroll
        for (int r=0;r<32;r++) acc[r] += sS[(hb+3*r)*96 + k]*dl;
    }
    size_t base = ((size_t)b*CC + c)*NN;
    #pragma unroll
    for (int r=0;r<32;r++){
        bf16 h,l; split_bf(acc[r],h,l);
        size_t idx = base + (hb+3*r)*96 + w;
        gEh[idx]=h; gEl[idx]=l;
    }
}

/* ---------------- tensor-core GEMM, bf16x3, 128x128 tile, 3-stage single-sync pipeline ----
   out[b,o,n] = act( sum_k W[o][k] * B[k][b,n] ), B = [seg0;seg1;seg2] (hi/lo pairs)
   A (weights) [o][KTOT] k-contiguous bf16 hi/lo; PERB: per-batch A.
   Dynamic smem: 3 stages x (Ah[128][24]+Al+Bh[16][136]+Bl) = 62976 bytes. */
#define ST 3
#define SMA (128*24)
#define SMB (16*136)
#define TG_SMEM (ST*2*(SMA+SMB)*2)   /* 62976 bytes */

template<int ACT, int OUTPAIR, int KTOT, int PERB, int S0, int S1, int S2>
__global__ __launch_bounds__(256) void tcgemm(
    const bf16* __restrict__ Wh, const bf16* __restrict__ Wl,
    const bf16* __restrict__ p0h, const bf16* __restrict__ p0l,
    const bf16* __restrict__ p1h, const bf16* __restrict__ p1l,
    const bf16* __restrict__ p2h, const bf16* __restrict__ p2l,
    float* __restrict__ outf, bf16* __restrict__ outh, bf16* __restrict__ outl)
{
    constexpr int NT = KTOT/16;
    extern __shared__ bf16 dsm[];
    bf16* sAh = dsm;                 /* [ST][128][24] */
    bf16* sAl = sAh + ST*SMA;
    bf16* sBh = sAl + ST*SMA;        /* [ST][16][136] */
    bf16* sBl = sBh + ST*SMB;

    int tid = threadIdx.x;
    int j0 = blockIdx.x * 128;
    int b  = j0 / NN;
    int n0 = j0 - b*NN;
    int o0 = blockIdx.y * 128;
    int lane = tid & 31, w = tid >> 5;
    int wm = (w >> 2) * 64, wn = (w & 3) * 32;
    int g = lane >> 2, t4 = lane & 3;
    int ra = lane & 15, ca = (lane >> 4) * 8;

    float acc[4][4][4];
    #pragma unroll
    for (int mi=0;mi<4;mi++)
        #pragma unroll
        for (int ni=0;ni<4;ni++)
            #pragma unroll
            for (int r=0;r<4;r++) acc[mi][ni][r]=0.f;

    const bf16* WhB = Wh + (PERB ? (size_t)b*CC*KTOT : 0);
    const bf16* WlB = Wl + (PERB ? (size_t)b*CC*KTOT : 0);

    auto fill = [&](int kt, int stg){
        /* A: 128 rows x 16 k, hi+lo; 16B chunks: 512 total, 2/thread */
        #pragma unroll
        for (int i = tid; i < 512; i += 256){
            int arr = i >> 8, r = i & 255, o = r >> 1, half = r & 1;
            const bf16* src = (arr ? WlB : WhB) + (size_t)(o0 + o)*KTOT + kt + half*8;
            bf16* dst = (arr ? sAl : sAh) + stg*SMA + o*24 + half*8;
            cpasync16(scvt(dst), src);
        }
        /* B: 16 rows x 128 n, hi+lo; 16B chunks: 512 total, 2/thread */
        #pragma unroll
        for (int i = tid; i < 512; i += 256){
            int arr = i >> 8, r = i & 255, k = r >> 4, ch = r & 15;
            int kg = kt + k;
            const bf16 *ph, *pl; int kr, S;
            if (kg < S0){ ph=p0h; pl=p0l; kr=kg; S=S0; }
            else if (kg < S0+S1){ ph=p1h; pl=p1l; kr=kg-S0; S=S1; }
            else { ph=p2h; pl=p2l; kr=kg-S0-S1; S=(S2>0?S2:1); }
            const bf16* src = (arr ? pl : ph) + ((size_t)b*S + kr)*NN + n0 + ch*8;
            bf16* dst = (arr ? sBl : sBh) + stg*SMB + k*136 + ch*8;
            cpasync16(scvt(dst), src);
        }
    };

    /* prologue: stages 0,1 in flight */
    fill(0, 0); cpcommit();
    fill(16, 1); cpcommit();

    #pragma unroll 1
    for (int t = 0; t < NT; t++){
        cpwait1();          /* tiles 0..t complete (<=1 group outstanding) */
        __syncthreads();    /* data visible to all; stage (t-1)%ST free to refill */
        if (t + 2 < NT) fill((t+2)*16, (t+2)%ST);
        cpcommit();         /* always commit (possibly empty) to keep group count exact */

        int stg = t % ST;
        const bf16* Ah = sAh + stg*SMA;
        const bf16* Al = sAl + stg*SMA;
        const bf16* Bh = sBh + stg*SMB;
        const bf16* Bl = sBl + stg*SMB;

        unsigned ah[4][4], al[4][4], bh[4][2], bl[4][2];
        #pragma unroll
        for (int mi=0;mi<4;mi++){
            ldsm4(ah[mi][0],ah[mi][1],ah[mi][2],ah[mi][3],
                  scvt(&Ah[(wm + mi*16 + ra)*24 + ca]));
            ldsm4(al[mi][0],al[mi][1],al[mi][2],al[mi][3],
                  scvt(&Al[(wm + mi*16 + ra)*24 + ca]));
        }
        #pragma unroll
        for (int nb=0; nb<2; nb++){
            ldsm4t(bh[2*nb][0],bh[2*nb][1],bh[2*nb+1][0],bh[2*nb+1][1],
                   scvt(&Bh[ra*136 + wn + nb*16 + ca]));
            ldsm4t(bl[2*nb][0],bl[2*nb][1],bl[2*nb+1][0],bl[2*nb+1][1],
                   scvt(&Bl[ra*136 + wn + nb*16 + ca]));
        }
        #pragma unroll
        for (int mi=0;mi<4;mi++)
            #pragma unroll
            for (int ni=0;ni<4;ni++){
                mma16816(acc[mi][ni], ah[mi], bh[ni]);
                mma16816(acc[mi][ni], al[mi], bh[ni]);
                mma16816(acc[mi][ni], ah[mi], bl[ni]);
            }
    }

    /* epilogue */
    #pragma unroll
    for (int mi=0;mi<4;mi++){
        int oa = o0 + wm + mi*16 + g;
        #pragma unroll
        for (int ni=0;ni<4;ni++){
            int n = n0 + wn + ni*8 + 2*t4;
            float v0=acc[mi][ni][0], v1=acc[mi][ni][1], v2=acc[mi][ni][2], v3=acc[mi][ni][3];
            if (ACT==1){ v0=lrelu_f(v0); v1=lrelu_f(v1); v2=lrelu_f(v2); v3=lrelu_f(v3); }
            if (ACT==2){
                v0=1.f/(1.f+expf(-v0)); v1=1.f/(1.f+expf(-v1));
                v2=1.f/(1.f+expf(-v2)); v3=1.f/(1.f+expf(-v3));
            }
            size_t i0 = ((size_t)b*CC + oa    )*NN + n;
            size_t i1 = ((size_t)b*CC + oa + 8)*NN + n;
            if (OUTPAIR){
                bf16 h0,l0,h1,l1;
                split_bf(v0,h0,l0); split_bf(v1,h1,l1);
                *(unsigned*)&outh[i0] = (unsigned)__bfloat16_as_ushort(h0) | ((unsigned)__bfloat16_as_ushort(h1)<<16);
                *(unsigned*)&outl[i0] = (unsigned)__bfloat16_as_ushort(l0) | ((unsigned)__bfloat16_as_ushort(l1)<<16);
                split_bf(v2,h0,l0); split_bf(v3,h1,l1);
                *(unsigned*)&outh[i1] = (unsigned)__bfloat16_as_ushort(h0) | ((unsigned)__bfloat16_as_ushort(h1)<<16);
                *(unsigned*)&outl[i1] = (unsigned)__bfloat16_as_ushort(l0) | ((unsigned)__bfloat16_as_ushort(l1)<<16);
            } else {
                float2 u; u.x=v0; u.y=v1; *(float2*)&outf[i0] = u;
                u.x=v2; u.y=v3;           *(float2*)&outf[i1] = u;
            }
        }
    }
}

/* ---------------- launch ---------------- */
extern "C" void kernel_launch(void* const* d_in, const int* in_sizes, int n_in,
                              void* d_out, int out_size)
{
    const float* x      = (const float*)d_in[0];
    const float* w_f    = (const float*)d_in[1];
    const float* w_beta = (const float*)d_in[2];
    const float* w1     = (const float*)d_in[3];
    const float* w3     = (const float*)d_in[4];
    const float* w5     = (const float*)d_in[5];
    const float* w7     = (const float*)d_in[6];
    const float* w_a2b  = (const float*)d_in[7];
    const float* w_f2c  = (const float*)d_in[8];
    const float* w_f2d  = (const float*)d_in[9];
    const float* w_e    = (const float*)d_in[10];
    const float* w_h    = (const float*)d_in[11];
    const float* w_m    = (const float*)d_in[12];
    const float* w_hm   = (const float*)d_in[13];
    float* out = (float*)d_out;

    bf16 *pFh,*pFl,*pEh,*pEl,*pXh,*pXl,*pHhh,*pHhl,*pMh,*pMl;
    bf16 *pWHhH,*pWHhL,*pWMH,*pWML,*pWHMH,*pWHML;
    cudaGetSymbolAddress((void**)&pFh,  gFh);   cudaGetSymbolAddress((void**)&pFl,  gFl);
    cudaGetSymbolAddress((void**)&pEh,  gEh);   cudaGetSymbolAddress((void**)&pEl,  gEl);
    cudaGetSymbolAddress((void**)&pXh,  gXh);   cudaGetSymbolAddress((void**)&pXl,  gXl);
    cudaGetSymbolAddress((void**)&pHhh, gHhh);  cudaGetSymbolAddress((void**)&pHhl, gHhl);
    cudaGetSymbolAddress((void**)&pMh,  gMh);   cudaGetSymbolAddress((void**)&pMl,  gMl);
    cudaGetSymbolAddress((void**)&pWHhH,gWHhH); cudaGetSymbolAddress((void**)&pWHhL,gWHhL);
    cudaGetSymbolAddress((void**)&pWMH, gWMH);  cudaGetSymbolAddress((void**)&pWML, gWML);
    cudaGetSymbolAddress((void**)&pWHMH,gWHMH); cudaGetSymbolAddress((void**)&pWHML,gWHML);

    cudaFuncSetAttribute(k_Esp, cudaFuncAttributeMaxDynamicSharedMemorySize, 2*NN*sizeof(float));
    cudaFuncSetAttribute((const void*)tcgemm<1,1,KHH,1, 16,256,256>,
                         cudaFuncAttributeMaxDynamicSharedMemorySize, TG_SMEM);
    cudaFuncSetAttribute((const void*)tcgemm<2,1,512,0, 256,256,0>,
                         cudaFuncAttributeMaxDynamicSharedMemorySize, TG_SMEM);
    cudaFuncSetAttribute((const void*)tcgemm<1,0,512,0, 256,256,0>,
                         cudaFuncAttributeMaxDynamicSharedMemorySize, TG_SMEM);

    dim3 gtile(BNT/128, 2);

    /* weight prep */
    k_prepW <<<CC, 256>>>(w_h, w_beta, w_e);
    k_convW <<<CC*2*CC/256, 256>>>(w_m,  pWMH,  pWML);
    k_convW <<<CC*2*CC/256, 256>>>(w_hm, pWHMH, pWHML);

    /* channel-attention path (also emits Xh/Xl, Fh/Fl) */
    k_Fused<<<dim3(NN/256, BB), 256>>>(x, w_f, w_a2b);
    k_L    <<<dim3(CC, BB),     256>>>(x);
    k_softS<<<dim3(KK, BB),     256>>>();
    k_prepWef<<<dim3(CC, BB),   128>>>();

    /* spatial-attention path */
    k_F4Cm<<<dim3(NN/256, BB), 256>>>(w1, w3, w5, w7, w_f2c);
    k_Ssp <<<dim3(HH, BB), 128>>>();
    k_Esp <<<dim3(CC, BB), 288, 2*NN*sizeof(float)>>>(w_f2d);

    /* tensor-core head: Hh, M, H_M (3-stage pipelined) */
    tcgemm<1,1,KHH,1, 16,256,256><<<gtile,256,TG_SMEM>>>(pWHhH,pWHhL, pFh,pFl, pEh,pEl, pXh,pXl,
                                                 (float*)0, pHhh, pHhl);
    tcgemm<2,1,512,0, 256,256,0><<<gtile,256,TG_SMEM>>>(pWMH,pWML,  pHhh,pHhl, pXh,pXl, pXh,pXl,
                                                 (float*)0, pMh, pMl);
    tcgemm<1,0,512,0, 256,256,0><<<gtile,256,TG_SMEM>>>(pWHMH,pWHML, pHhh,pHhl, pMh,pMl, pMh,pMl,
                                                 out, (bf16*)0, (bf16*)0);
}

// round 15
// speedup vs baseline: 1.1037x; 1.0225x over previous
#include <cuda_runtime.h>
#include <cuda_bf16.h>
#include <cstdint>

#define BB 8
#define CC 256
#define HH 96
#define WW 96
#define NN (HH*WW)        /* 9216 */
#define KK 16
#define BNT (BB*NN)       /* 73728 */
#define KHH 528           /* 16 + 256 + 256 */

typedef __nv_bfloat16 bf16;

/* ---------------- scratch (device globals) ---------------- */
__device__ float gF   [BB*KK*NN];     /* fp32 F for k_L */
__device__ float gL   [BB*KK*CC];
__device__ float gS   [BB*KK*CC];
__device__ float gAvg [BB*NN];
__device__ float gMax [BB*NN];
__device__ float gBm  [BB*NN];
__device__ float gF4  [BB*4*NN];
__device__ float gCm  [BB*NN];
__device__ float gSsp [BB*HH*HH];
__device__ float gWb  [CC*CC];        /* Wb' = w_h1 . w_beta (fp32, feeds prepWef) */

/* bf16 hi/lo operand arrays, layout [b][k][n] (n contiguous) */
__device__ bf16 gFh [BB*KK*NN],  gFl [BB*KK*NN];
__device__ bf16 gEh [BB*CC*NN],  gEl [BB*CC*NN];   /* Esp */
__device__ bf16 gXh [BB*CC*NN],  gXl [BB*CC*NN];   /* x   */
__device__ bf16 gHhh[BB*CC*NN],  gHhl[BB*CC*NN];   /* Hh  */
__device__ bf16 gMh [BB*CC*NN],  gMl [BB*CC*NN];   /* M   */

/* bf16 hi/lo weights, layout [o][K] (K contiguous) */
__device__ bf16 gWHhH[BB*CC*KHH], gWHhL[BB*CC*KHH];  /* per-batch [b][o][528] */
__device__ bf16 gWMH [CC*2*CC],   gWML [CC*2*CC];
__device__ bf16 gWHMH[CC*2*CC],   gWHML[CC*2*CC];

__device__ __forceinline__ float lrelu_f(float v){ return v >= 0.f ? v : 0.001f*v; }

__device__ __forceinline__ void split_bf(float v, bf16& h, bf16& l){
    h = __float2bfloat16_rn(v);
    l = __float2bfloat16_rn(v - __bfloat162float(h));
}

__device__ __forceinline__ void cpasync16(unsigned int saddr, const void* g){
    asm volatile("cp.async.ca.shared.global [%0], [%1], 16;\n" :: "r"(saddr), "l"(g));
}
__device__ __forceinline__ void cpcommit(){ asm volatile("cp.async.commit_group;\n"); }
__device__ __forceinline__ void cpwait1(){ asm volatile("cp.async.wait_group 1;\n"); }

__device__ __forceinline__ unsigned scvt(const void* p){
    return (unsigned)__cvta_generic_to_shared(p);
}
__device__ __forceinline__ void ldsm4(unsigned &r0, unsigned &r1, unsigned &r2, unsigned &r3,
                                      unsigned saddr){
    asm volatile("ldmatrix.sync.aligned.m8n8.x4.shared.b16 {%0,%1,%2,%3}, [%4];"
        : "=r"(r0), "=r"(r1), "=r"(r2), "=r"(r3) : "r"(saddr));
}
__device__ __forceinline__ void ldsm4t(unsigned &r0, unsigned &r1, unsigned &r2, unsigned &r3,
                                       unsigned saddr){
    asm volatile("ldmatrix.sync.aligned.m8n8.x4.trans.shared.b16 {%0,%1,%2,%3}, [%4];"
        : "=r"(r0), "=r"(r1), "=r"(r2), "=r"(r3) : "r"(saddr));
}

__device__ __forceinline__ void mma16816(float* c, const unsigned* a, const unsigned* b){
    asm volatile(
        "mma.sync.aligned.m16n8k16.row.col.f32.bf16.bf16.f32 "
        "{%0,%1,%2,%3}, {%4,%5,%6,%7}, {%8,%9}, {%0,%1,%2,%3};"
        : "+f"(c[0]), "+f"(c[1]), "+f"(c[2]), "+f"(c[3])
        : "r"(a[0]), "r"(a[1]), "r"(a[2]), "r"(a[3]), "r"(b[0]), "r"(b[1]));
}

/* ---------------- fused: F (fp32 + hi/lo), X hi/lo, avg, max, Bm in ONE pass ---------------- */
__global__ void k_Fused(const float* __restrict__ x, const float* __restrict__ w_f,
                        const float* __restrict__ w_a2b){
    __shared__ float wfs[KK*CC];
    __shared__ float wa[CC];
    int tid = threadIdx.x;
    for (int i = tid; i < KK*CC; i += 256) wfs[i] = w_f[i];
    for (int i = tid; i < CC; i += 256)    wa[i]  = w_a2b[i];
    __syncthreads();
    int b = blockIdx.y;
    int n = blockIdx.x*256 + tid;
    float acc[KK];
    #pragma unroll
    for (int k=0;k<KK;k++) acc[k]=0.f;
    float s=0.f, mx=-1e30f, bm=0.f;
    const float* xb = x + (size_t)b*CC*NN + n;
    for (int c=0;c<CC;c++){
        float xv = xb[(size_t)c*NN];
        s += xv; mx = fmaxf(mx, xv); bm += wa[c]*xv;
        bf16 h,l; split_bf(xv,h,l);
        size_t xi = ((size_t)b*CC+c)*NN + n;
        gXh[xi]=h; gXl[xi]=l;
        #pragma unroll
        for (int k=0;k<KK;k++) acc[k] += wfs[k*CC+c]*xv;
    }
    #pragma unroll
    for (int k=0;k<KK;k++){
        size_t idx = ((size_t)b*KK+k)*NN + n;
        gF[idx] = acc[k];
        bf16 h,l; split_bf(acc[k],h,l);
        gFh[idx]=h; gFl[idx]=l;
    }
    gAvg[b*NN+n]=s*(1.f/CC);
    gMax[b*NN+n]=mx;
    gBm [b*NN+n]=lrelu_f(bm);
}

/* ---------------- L[b,k,c] = sum_n F[b,k,n] * x[b,c,n] ---------------- */
__global__ void k_L(const float* __restrict__ x){
    int c = blockIdx.x, b = blockIdx.y, tid = threadIdx.x;
    float acc[KK];
    #pragma unroll
    for (int k=0;k<KK;k++) acc[k]=0.f;
    const float* xr = x + ((size_t)b*CC + c)*NN;
    const float* Fb = gF + (size_t)b*KK*NN;
    for (int n=tid; n<NN; n+=256){
        float xv = xr[n];
        #pragma unroll
        for (int k=0;k<KK;k++) acc[k] += Fb[(size_t)k*NN+n]*xv;
    }
    #pragma unroll
    for (int off=16; off; off>>=1){
        #pragma unroll
        for (int k=0;k<KK;k++) acc[k] += __shfl_down_sync(0xffffffffu, acc[k], off);
    }
    __shared__ float red[KK][8];
    int lane = tid & 31, wp = tid >> 5;
    if (lane == 0){
        #pragma unroll
        for (int k=0;k<KK;k++) red[k][wp] = acc[k];
    }
    __syncthreads();
    if (tid < KK){
        float s = 0.f;
        #pragma unroll
        for (int w=0;w<8;w++) s += red[tid][w];
        gL[((size_t)b*KK+tid)*CC + c] = s;
    }
}

/* ---------------- softmax over c ---------------- */
__global__ void k_softS(){
    int k = blockIdx.x, b = blockIdx.y, c = threadIdx.x;
    int lane = c & 31, wp = c >> 5;
    __shared__ float sm[8];
    float v = gL[((size_t)b*KK+k)*CC + c];
    float m = v;
    #pragma unroll
    for (int off=16; off; off>>=1) m = fmaxf(m, __shfl_xor_sync(0xffffffffu, m, off));
    if (lane == 0) sm[wp] = m;
    __syncthreads();
    m = sm[0];
    #pragma unroll
    for (int i=1;i<8;i++) m = fmaxf(m, sm[i]);
    float e = expf(v - m);
    float s = e;
    #pragma unroll
    for (int off=16; off; off>>=1) s += __shfl_xor_sync(0xffffffffu, s, off);
    __syncthreads();
    if (lane == 0) sm[wp] = s;
    __syncthreads();
    s = 0.f;
    #pragma unroll
    for (int i=0;i<8;i++) s += sm[i];
    gS[((size_t)b*KK+k)*CC + c] = e / s;
}

/* ---------------- folded weights into gWHh (segments Esp, x) + gWb ---------------- */
__global__ void k_prepW(const float* __restrict__ w_h, const float* __restrict__ w_beta,
                        const float* __restrict__ w_e){
    __shared__ float whr[2*CC];
    int o = blockIdx.x, tid = threadIdx.x;
    whr[tid]     = w_h[(size_t)o*2*CC + tid];
    whr[tid+CC]  = w_h[(size_t)o*2*CC + CC + tid];
    __syncthreads();
    int c = tid;
    float a1 = 0.f, a2 = 0.f;
    for (int j=0;j<CC;j++){
        a1 += whr[j]    * w_beta[j*CC + c];
        a2 += whr[CC+j] * w_e   [j*CC + c];
    }
    gWb[o*CC + c] = a1;
    float wx = whr[c] + whr[CC+c];
    bf16 h2,l2,hx,lx;
    split_bf(a2,h2,l2); split_bf(wx,hx,lx);
    for (int b=0;b<BB;b++){
        size_t base = ((size_t)b*CC + o)*KHH;
        gWHhH[base + 16  + c] = h2; gWHhL[base + 16  + c] = l2;
        gWHhH[base + 272 + c] = hx; gWHhL[base + 272 + c] = lx;
    }
}

/* ---------------- per-batch W_EF segment: gWHh[b][o][k<16] ---------------- */
__global__ void k_prepWef(){
    int o = blockIdx.x, b = blockIdx.y, tid = threadIdx.x;  /* 128 threads */
    float acc[KK];
    #pragma unroll
    for (int k=0;k<KK;k++) acc[k]=0.f;
    for (int c=tid; c<CC; c+=128){
        float wv = gWb[o*CC + c];
        #pragma unroll
        for (int k=0;k<KK;k++) acc[k] += wv * gS[((size_t)b*KK+k)*CC + c];
    }
    #pragma unroll
    for (int off=16; off; off>>=1){
        #pragma unroll
        for (int k=0;k<KK;k++) acc[k] += __shfl_down_sync(0xffffffffu, acc[k], off);
    }
    __shared__ float red[KK][4];
    int lane = tid & 31, wp = tid >> 5;
    if (lane == 0){
        #pragma unroll
        for (int k=0;k<KK;k++) red[k][wp] = acc[k];
    }
    __syncthreads();
    if (tid < KK){
        float s = red[tid][0]+red[tid][1]+red[tid][2]+red[tid][3];
        bf16 h,l; split_bf(s,h,l);
        size_t base = ((size_t)b*CC + o)*KHH;
        gWHhH[base + tid] = h;
        gWHhL[base + tid] = l;
    }
}

/* ---------------- convert 256x512 fp32 weight -> bf16 hi/lo (same layout) ---------------- */
__global__ void k_convW(const float* __restrict__ w, bf16* __restrict__ wh, bf16* __restrict__ wl){
    int i = blockIdx.x*256 + threadIdx.x;
    bf16 h,l; split_bf(w[i],h,l);
    wh[i]=h; wl[i]=l;
}

/* ---------------- avg/max convs 1/3/5/7 -> F4, Cm ---------------- */
__global__ void k_F4Cm(const float* __restrict__ w1, const float* __restrict__ w3,
                       const float* __restrict__ w5, const float* __restrict__ w7,
                       const float* __restrict__ wf2c){
    __shared__ float s1w[2], s3w[18], s5w[50], s7w[98], c4[4];
    int tid = threadIdx.x;
    if (tid < 2)  s1w[tid]=w1[tid];
    if (tid < 18) s3w[tid]=w3[tid];
    if (tid < 50) s5w[tid]=w5[tid];
    if (tid < 98) s7w[tid]=w7[tid];
    if (tid < 4)  c4[tid]=wf2c[tid];
    __syncthreads();
    int b = blockIdx.y, n = blockIdx.x*256 + tid;
    int h = n / WW, w = n - h*WW;
    const float* av  = gAvg + b*NN;
    const float* mxp = gMax + b*NN;
    float s1=0.f, s3=0.f, s5=0.f, s7=0.f;
    #pragma unroll
    for (int dy=-3; dy<=3; dy++){
        int y = h+dy; if (y<0 || y>=HH) continue;
        #pragma unroll
        for (int dx=-3; dx<=3; dx++){
            int x2 = w+dx; if (x2<0 || x2>=WW) continue;
            float a = av[y*WW+x2], m = mxp[y*WW+x2];
            s7 += a*s7w[(dy+3)*7+dx+3] + m*s7w[49+(dy+3)*7+dx+3];
            if (dy>=-2 && dy<=2 && dx>=-2 && dx<=2)
                s5 += a*s5w[(dy+2)*5+dx+2] + m*s5w[25+(dy+2)*5+dx+2];
            if (dy>=-1 && dy<=1 && dx>=-1 && dx<=1)
                s3 += a*s3w[(dy+1)*3+dx+1] + m*s3w[9+(dy+1)*3+dx+1];
            if (dy==0 && dx==0)
                s1 = a*s1w[0] + m*s1w[1];
        }
    }
    float f0=lrelu_f(s1), f1=lrelu_f(s3), f2=lrelu_f(s5), f3=lrelu_f(s7);
    gF4[((size_t)b*4+0)*NN+n]=f0;
    gF4[((size_t)b*4+1)*NN+n]=f1;
    gF4[((size_t)b*4+2)*NN+n]=f2;
    gF4[((size_t)b*4+3)*NN+n]=f3;
    gCm[b*NN+n] = lrelu_f(c4[0]*f0 + c4[1]*f1 + c4[2]*f2 + c4[3]*f3);
}

/* ---------------- Ssp ---------------- */
__global__ void k_Ssp(){
    int h = blockIdx.x, b = blockIdx.y, tid = threadIdx.x;
    __shared__ float sm[4];
    float lg = -1e30f;
    if (tid < HH){
        float a = 0.f;
        const float* bm = gBm + b*NN + h*WW;
        const float* cm = gCm + b*NN;
        for (int w=0; w<WW; w++) a += bm[w]*cm[w*HH + tid];
        lg = a;
    }
    int lane = tid & 31, wp = tid >> 5;
    float m = lg;
    #pragma unroll
    for (int off=16; off; off>>=1) m = fmaxf(m, __shfl_xor_sync(0xffffffffu, m, off));
    if (lane == 0) sm[wp] = m;
    __syncthreads();
    m = fmaxf(fmaxf(sm[0],sm[1]), fmaxf(sm[2],sm[3]));
    float e = (tid < HH) ? expf(lg - m) : 0.f;
    float s = e;
    #pragma unroll
    for (int off=16; off; off>>=1) s += __shfl_xor_sync(0xffffffffu, s, off);
    __syncthreads();
    if (lane == 0) sm[wp] = s;
    __syncthreads();
    s = sm[0]+sm[1]+sm[2]+sm[3];
    if (tid < HH) gSsp[((size_t)b*HH + h)*HH + tid] = e / s;
}

/* ---------------- Esp -> bf16 hi/lo ---------------- */
__global__ void k_Esp(const float* __restrict__ w_f2d){
    extern __shared__ float sh[];
    float* sS = sh;
    float* sD = sh + NN;
    int c = blockIdx.x, b = blockIdx.y, tid = threadIdx.x;
    float d0=w_f2d[c*4+0], d1=w_f2d[c*4+1], d2=w_f2d[c*4+2], d3=w_f2d[c*4+3];
    const float* f4b = gF4 + (size_t)b*4*NN;
    const float* ssp = gSsp + (size_t)b*NN;
    for (int i=tid; i<NN; i+=288){
        sS[i] = ssp[i];
        float v = d0*f4b[i] + d1*f4b[NN+i] + d2*f4b[2*NN+i] + d3*f4b[3*NN+i];
        sD[i] = lrelu_f(v);
    }
    __syncthreads();
    int w = tid % 96, hb = tid / 96;
    float acc[32];
    #pragma unroll
    for (int r=0;r<32;r++) acc[r]=0.f;
    for (int k=0;k<96;k++){
        float dl = sD[k*96 + w];
        #pragma unroll
        for (int r=0;r<32;r++) acc[r] += sS[(hb+3*r)*96 + k]*dl;
    }
    size_t base = ((size_t)b*CC + c)*NN;
    #pragma unroll
    for (int r=0;r<32;r++){
        bf16 h,l; split_bf(acc[r],h,l);
        size_t idx = base + (hb+3*r)*96 + w;
        gEh[idx]=h; gEl[idx]=l;
    }
}

/* ---------------- tensor-core GEMM, bf16x3, 128x128 tile, 3-stage pipeline, 2 CTAs/SM ----
   out[b,o,n] = act( sum_k W[o][k] * B[k][b,n] ), B = [seg0;seg1;seg2] (hi/lo pairs)
   A (weights) [o][KTOT] k-contiguous bf16 hi/lo; PERB: per-batch A.
   Dynamic smem: 3 stages x (Ah[128][24]+Al+Bh[16][136]+Bl) = 62976 bytes. */
#define ST 3
#define SMA (128*24)
#define SMB (16*136)
#define TG_SMEM (ST*2*(SMA+SMB)*2)   /* 62976 bytes */

template<int ACT, int OUTPAIR, int KTOT, int PERB, int S0, int S1, int S2>
__global__ __launch_bounds__(256, 2) void tcgemm(
    const bf16* __restrict__ Wh, const bf16* __restrict__ Wl,
    const bf16* __restrict__ p0h, const bf16* __restrict__ p0l,
    const bf16* __restrict__ p1h, const bf16* __restrict__ p1l,
    const bf16* __restrict__ p2h, const bf16* __restrict__ p2l,
    float* __restrict__ outf, bf16* __restrict__ outh, bf16* __restrict__ outl)
{
    constexpr int NT = KTOT/16;
    extern __shared__ bf16 dsm[];
    bf16* sAh = dsm;                 /* [ST][128][24] */
    bf16* sAl = sAh + ST*SMA;
    bf16* sBh = sAl + ST*SMA;        /* [ST][16][136] */
    bf16* sBl = sBh + ST*SMB;

    int tid = threadIdx.x;
    int j0 = blockIdx.x * 128;
    int b  = j0 / NN;
    int n0 = j0 - b*NN;
    int o0 = blockIdx.y * 128;
    int lane = tid & 31, w = tid >> 5;
    int wm = (w >> 2) * 64, wn = (w & 3) * 32;
    int g = lane >> 2, t4 = lane & 3;
    int ra = lane & 15, ca = (lane >> 4) * 8;

    float acc[4][4][4];
    #pragma unroll
    for (int mi=0;mi<4;mi++)
        #pragma unroll
        for (int ni=0;ni<4;ni++)
            #pragma unroll
            for (int r=0;r<4;r++) acc[mi][ni][r]=0.f;

    const bf16* WhB = Wh + (PERB ? (size_t)b*CC*KTOT : 0);
    const bf16* WlB = Wl + (PERB ? (size_t)b*CC*KTOT : 0);

    auto fill = [&](int kt, int stg){
        /* A: 128 rows x 16 k, hi+lo; 16B chunks: 512 total, 2/thread */
        #pragma unroll
        for (int i = tid; i < 512; i += 256){
            int arr = i >> 8, r = i & 255, o = r >> 1, half = r & 1;
            const bf16* src = (arr ? WlB : WhB) + (size_t)(o0 + o)*KTOT + kt + half*8;
            bf16* dst = (arr ? sAl : sAh) + stg*SMA + o*24 + half*8;
            cpasync16(scvt(dst), src);
        }
        /* B: 16 rows x 128 n, hi+lo; 16B chunks: 512 total, 2/thread */
        #pragma unroll
        for (int i = tid; i < 512; i += 256){
            int arr = i >> 8, r = i & 255, k = r >> 4, ch = r & 15;
            int kg = kt + k;
            const bf16 *ph, *pl; int kr, S;
            if (kg < S0){ ph=p0h; pl=p0l; kr=kg; S=S0; }
            else if (kg < S0+S1){ ph=p1h; pl=p1l; kr=kg-S0; S=S1; }
            else { ph=p2h; pl=p2l; kr=kg-S0-S1; S=(S2>0?S2:1); }
            const bf16* src = (arr ? pl : ph) + ((size_t)b*S + kr)*NN + n0 + ch*8;
            bf16* dst = (arr ? sBl : sBh) + stg*SMB + k*136 + ch*8;
            cpasync16(scvt(dst), src);
        }
    };

    /* prologue: stages 0,1 in flight */
    fill(0, 0); cpcommit();
    fill(16, 1); cpcommit();

    #pragma unroll 1
    for (int t = 0; t < NT; t++){
        cpwait1();          /* tiles 0..t complete (<=1 group outstanding) */
        __syncthreads();    /* data visible to all; stage (t-1)%ST free to refill */
        if (t + 2 < NT) fill((t+2)*16, (t+2)%ST);
        cpcommit();         /* always commit (possibly empty) to keep group count exact */

        int stg = t % ST;
        const bf16* Ah = sAh + stg*SMA;
        const bf16* Al = sAl + stg*SMA;
        const bf16* Bh = sBh + stg*SMB;
        const bf16* Bl = sBl + stg*SMB;

        unsigned ah[4][4], al[4][4], bh[4][2], bl[4][2];
        #pragma unroll
        for (int mi=0;mi<4;mi++){
            ldsm4(ah[mi][0],ah[mi][1],ah[mi][2],ah[mi][3],
                  scvt(&Ah[(wm + mi*16 + ra)*24 + ca]));
            ldsm4(al[mi][0],al[mi][1],al[mi][2],al[mi][3],
                  scvt(&Al[(wm + mi*16 + ra)*24 + ca]));
        }
        #pragma unroll
        for (int nb=0; nb<2; nb++){
            ldsm4t(bh[2*nb][0],bh[2*nb][1],bh[2*nb+1][0],bh[2*nb+1][1],
                   scvt(&Bh[ra*136 + wn + nb*16 + ca]));
            ldsm4t(bl[2*nb][0],bl[2*nb][1],bl[2*nb+1][0],bl[2*nb+1][1],
                   scvt(&Bl[ra*136 + wn + nb*16 + ca]));
        }
        #pragma unroll
        for (int mi=0;mi<4;mi++)
            #pragma unroll
            for (int ni=0;ni<4;ni++){
                mma16816(acc[mi][ni], ah[mi], bh[ni]);
                mma16816(acc[mi][ni], al[mi], bh[ni]);
                mma16816(acc[mi][ni], ah[mi], bl[ni]);
            }
    }

    /* epilogue */
    #pragma unroll
    for (int mi=0;mi<4;mi++){
        int oa = o0 + wm + mi*16 + g;
        #pragma unroll
        for (int ni=0;ni<4;ni++){
            int n = n0 + wn + ni*8 + 2*t4;
            float v0=acc[mi][ni][0], v1=acc[mi][ni][1], v2=acc[mi][ni][2], v3=acc[mi][ni][3];
            if (ACT==1){ v0=lrelu_f(v0); v1=lrelu_f(v1); v2=lrelu_f(v2); v3=lrelu_f(v3); }
            if (ACT==2){
                v0=1.f/(1.f+expf(-v0)); v1=1.f/(1.f+expf(-v1));
                v2=1.f/(1.f+expf(-v2)); v3=1.f/(1.f+expf(-v3));
            }
            size_t i0 = ((size_t)b*CC + oa    )*NN + n;
            size_t i1 = ((size_t)b*CC + oa + 8)*NN + n;
            if (OUTPAIR){
                bf16 h0,l0,h1,l1;
                split_bf(v0,h0,l0); split_bf(v1,h1,l1);
                *(unsigned*)&outh[i0] = (unsigned)__bfloat16_as_ushort(h0) | ((unsigned)__bfloat16_as_ushort(h1)<<16);
                *(unsigned*)&outl[i0] = (unsigned)__bfloat16_as_ushort(l0) | ((unsigned)__bfloat16_as_ushort(l1)<<16);
                split_bf(v2,h0,l0); split_bf(v3,h1,l1);
                *(unsigned*)&outh[i1] = (unsigned)__bfloat16_as_ushort(h0) | ((unsigned)__bfloat16_as_ushort(h1)<<16);
                *(unsigned*)&outl[i1] = (unsigned)__bfloat16_as_ushort(l0) | ((unsigned)__bfloat16_as_ushort(l1)<<16);
            } else {
                float2 u; u.x=v0; u.y=v1; *(float2*)&outf[i0] = u;
                u.x=v2; u.y=v3;           *(float2*)&outf[i1] = u;
            }
        }
    }
}

/* ---------------- launch ---------------- */
extern "C" void kernel_launch(void* const* d_in, const int* in_sizes, int n_in,
                              void* d_out, int out_size)
{
    const float* x      = (const float*)d_in[0];
    const float* w_f    = (const float*)d_in[1];
    const float* w_beta = (const float*)d_in[2];
    const float* w1     = (const float*)d_in[3];
    const float* w3     = (const float*)d_in[4];
    const float* w5     = (const float*)d_in[5];
    const float* w7     = (const float*)d_in[6];
    const float* w_a2b  = (const float*)d_in[7];
    const float* w_f2c  = (const float*)d_in[8];
    const float* w_f2d  = (const float*)d_in[9];
    const float* w_e    = (const float*)d_in[10];
    const float* w_h    = (const float*)d_in[11];
    const float* w_m    = (const float*)d_in[12];
    const float* w_hm   = (const float*)d_in[13];
    float* out = (float*)d_out;

    bf16 *pFh,*pFl,*pEh,*pEl,*pXh,*pXl,*pHhh,*pHhl,*pMh,*pMl;
    bf16 *pWHhH,*pWHhL,*pWMH,*pWML,*pWHMH,*pWHML;
    cudaGetSymbolAddress((void**)&pFh,  gFh);   cudaGetSymbolAddress((void**)&pFl,  gFl);
    cudaGetSymbolAddress((void**)&pEh,  gEh);   cudaGetSymbolAddress((void**)&pEl,  gEl);
    cudaGetSymbolAddress((void**)&pXh,  gXh);   cudaGetSymbolAddress((void**)&pXl,  gXl);
    cudaGetSymbolAddress((void**)&pHhh, gHhh);  cudaGetSymbolAddress((void**)&pHhl, gHhl);
    cudaGetSymbolAddress((void**)&pMh,  gMh);   cudaGetSymbolAddress((void**)&pMl,  gMl);
    cudaGetSymbolAddress((void**)&pWHhH,gWHhH); cudaGetSymbolAddress((void**)&pWHhL,gWHhL);
    cudaGetSymbolAddress((void**)&pWMH, gWMH);  cudaGetSymbolAddress((void**)&pWML, gWML);
    cudaGetSymbolAddress((void**)&pWHMH,gWHMH); cudaGetSymbolAddress((void**)&pWHML,gWHML);

    cudaFuncSetAttribute(k_Esp, cudaFuncAttributeMaxDynamicSharedMemorySize, 2*NN*sizeof(float));
    cudaFuncSetAttribute((const void*)tcgemm<1,1,KHH,1, 16,256,256>,
                         cudaFuncAttributeMaxDynamicSharedMemorySize, TG_SMEM);
    cudaFuncSetAttribute((const void*)tcgemm<2,1,512,0, 256,256,0>,
                         cudaFuncAttributeMaxDynamicSharedMemorySize, TG_SMEM);
    cudaFuncSetAttribute((const void*)tcgemm<1,0,512,0, 256,256,0>,
                         cudaFuncAttributeMaxDynamicSharedMemorySize, TG_SMEM);

    dim3 gtile(BNT/128, 2);

    /* weight prep */
    k_prepW <<<CC, 256>>>(w_h, w_beta, w_e);
    k_convW <<<CC*2*CC/256, 256>>>(w_m,  pWMH,  pWML);
    k_convW <<<CC*2*CC/256, 256>>>(w_hm, pWHMH, pWHML);

    /* channel-attention path (also emits Xh/Xl, Fh/Fl) */
    k_Fused<<<dim3(NN/256, BB), 256>>>(x, w_f, w_a2b);
    k_L    <<<dim3(CC, BB),     256>>>(x);
    k_softS<<<dim3(KK, BB),     256>>>();
    k_prepWef<<<dim3(CC, BB),   128>>>();

    /* spatial-attention path */
    k_F4Cm<<<dim3(NN/256, BB), 256>>>(w1, w3, w5, w7, w_f2c);
    k_Ssp <<<dim3(HH, BB), 128>>>();
    k_Esp <<<dim3(CC, BB), 288, 2*NN*sizeof(float)>>>(w_f2d);

    /* tensor-core head: Hh, M, H_M (3-stage pipelined, 2 CTAs/SM) */
    tcgemm<1,1,KHH,1, 16,256,256><<<gtile,256,TG_SMEM>>>(pWHhH,pWHhL, pFh,pFl, pEh,pEl, pXh,pXl,
                                                 (float*)0, pHhh, pHhl);
    tcgemm<2,1,512,0, 256,256,0><<<gtile,256,TG_SMEM>>>(pWMH,pWML,  pHhh,pHhl, pXh,pXl, pXh,pXl,
                                                 (float*)0, pMh, pMl);
    tcgemm<1,0,512,0, 256,256,0><<<gtile,256,TG_SMEM>>>(pWHMH,pWHML, pHhh,pHhl, pMh,pMl, pMh,pMl,
                                                 out, (bf16*)0, (bf16*)0);
}